// round 3
// baseline (speedup 1.0000x reference)
#include <cuda_runtime.h>
#include <cuda_bf16.h>

#define CRF_B 512
#define CRF_T 1024
#define CRF_K 64

__device__ float g_per_batch[CRF_B];

__global__ void __launch_bounds__(32, 1) crf_forward_kernel(
    const float* __restrict__ emissions,       // [B, T, K] f32
    const float* __restrict__ transitions,     // [K, K] f32
    const float* __restrict__ start_t,         // [K] f32
    const float* __restrict__ end_t,           // [K] f32
    const int* __restrict__ tags,              // [B, T] int32 (harness promotes int64)
    const int* __restrict__ mask)              // [B, T] int32 (harness promotes bool)
{
    const int b = blockIdx.x;
    const int lane = threadIdx.x;
    const unsigned FULL = 0xffffffffu;

    const float* em = emissions + (size_t)b * CRF_T * CRF_K;
    const int* tg = tags + (size_t)b * CRF_T;
    const int* mk = mask + (size_t)b * CRF_T;

    // ---------------- numerator (gold-path score) ----------------
    float part = 0.f;
    int cnt = 0;
    for (int t = lane; t < CRF_T; t += 32) {
        int m = (mk[t] != 0) ? 1 : 0;
        cnt += m;
        if (t > 0 && m) {
            int tag  = tg[t];
            int ptag = tg[t - 1];
            part += em[t * CRF_K + tag] + transitions[ptag * CRF_K + tag];
        }
    }
    #pragma unroll
    for (int off = 16; off; off >>= 1) {
        part += __shfl_xor_sync(FULL, part, off);
        cnt  += __shfl_xor_sync(FULL, cnt,  off);
    }
    float numer = 0.f;
    if (lane == 0) {
        int tag0 = tg[0];
        numer = part + em[tag0] + start_t[tag0];
        int last = tg[cnt - 1];
        numer += end_t[last];
    }

    // ---------------- E = exp(transitions), 2 columns per thread in registers ----------------
    float E0[CRF_K];
    float E1[CRF_K];
    #pragma unroll
    for (int i = 0; i < CRF_K; i++) {
        E0[i] = __expf(transitions[i * CRF_K + lane]);
        E1[i] = __expf(transitions[i * CRF_K + lane + 32]);
    }

    // ---------------- forward recursion ----------------
    // alpha held relative; C accumulates the max shifts (denominator offset).
    float a0 = em[lane]      + start_t[lane];
    float a1 = em[lane + 32] + start_t[lane + 32];
    float C = 0.f;

    float e0 = em[CRF_K + lane];
    float e1 = em[CRF_K + lane + 32];

    for (int t = 1; t < CRF_T; ++t) {
        // prefetch next step's emissions
        float ne0 = 0.f, ne1 = 0.f;
        if (t + 1 < CRF_T) {
            ne0 = em[(t + 1) * CRF_K + lane];
            ne1 = em[(t + 1) * CRF_K + lane + 32];
        }

        // warp-wide max of alpha
        float m = fmaxf(a0, a1);
        #pragma unroll
        for (int off = 16; off; off >>= 1)
            m = fmaxf(m, __shfl_xor_sync(FULL, m, off));

        float p0 = __expf(a0 - m);
        float p1 = __expf(a1 - m);

        // s[j] = sum_i p[i] * E[i][j], split into 2 accumulators per state
        float s0a = 0.f, s0b = 0.f, s1a = 0.f, s1b = 0.f;
        #pragma unroll
        for (int i = 0; i < 32; i += 2) {
            float pa = __shfl_sync(FULL, p0, i);
            float pb = __shfl_sync(FULL, p0, i + 1);
            s0a += pa * E0[i];     s1a += pa * E1[i];
            s0b += pb * E0[i + 1]; s1b += pb * E1[i + 1];
        }
        #pragma unroll
        for (int i = 0; i < 32; i += 2) {
            float pa = __shfl_sync(FULL, p1, i);
            float pb = __shfl_sync(FULL, p1, i + 1);
            s0a += pa * E0[32 + i];     s1a += pa * E1[32 + i];
            s0b += pb * E0[33 + i];     s1b += pb * E1[33 + i];
        }

        float na0 = e0 + __logf(s0a + s0b);
        float na1 = e1 + __logf(s1a + s1b);

        if (mk[t] != 0) { a0 = na0; a1 = na1; C += m; }
        e0 = ne0; e1 = ne1;
    }

    // ---------------- final logsumexp with end transitions ----------------
    float f0 = a0 + end_t[lane];
    float f1 = a1 + end_t[lane + 32];
    float m2 = fmaxf(f0, f1);
    #pragma unroll
    for (int off = 16; off; off >>= 1)
        m2 = fmaxf(m2, __shfl_xor_sync(FULL, m2, off));
    float s = __expf(f0 - m2) + __expf(f1 - m2);
    #pragma unroll
    for (int off = 16; off; off >>= 1)
        s += __shfl_xor_sync(FULL, s, off);

    if (lane == 0) {
        float denom = C + m2 + __logf(s);
        g_per_batch[b] = denom - numer;
    }
}

__global__ void crf_reduce_kernel(float* __restrict__ out)
{
    __shared__ float sh[CRF_B];
    int t = threadIdx.x;
    sh[t] = g_per_batch[t];
    __syncthreads();
    #pragma unroll
    for (int s = CRF_B / 2; s > 0; s >>= 1) {
        if (t < s) sh[t] += sh[t + s];
        __syncthreads();
    }
    if (t == 0) out[0] = sh[0] * (1.0f / (float)CRF_B);
}

extern "C" void kernel_launch(void* const* d_in, const int* in_sizes, int n_in,
                              void* d_out, int out_size)
{
    const float* emissions   = (const float*)d_in[0];
    const float* transitions = (const float*)d_in[1];
    const float* start_t     = (const float*)d_in[2];
    const float* end_t       = (const float*)d_in[3];
    const int* tags          = (const int*)d_in[4];
    const int* mask          = (const int*)d_in[5];

    crf_forward_kernel<<<CRF_B, 32>>>(emissions, transitions, start_t, end_t, tags, mask);
    crf_reduce_kernel<<<1, CRF_B>>>((float*)d_out);
}

// round 5
// speedup vs baseline: 1.2696x; 1.2696x over previous
#include <cuda_runtime.h>
#include <cuda_bf16.h>

#define CRF_B 512
#define CRF_T 1024
#define CRF_K 64
#define WPB 4   // warps per block

__device__ float g_per_batch[CRF_B];

__global__ void __launch_bounds__(32 * WPB, 1) crf_forward_kernel(
    const float* __restrict__ emissions,       // [B, T, K] f32
    const float* __restrict__ transitions,     // [K, K] f32
    const float* __restrict__ start_t,         // [K] f32
    const float* __restrict__ end_t,           // [K] f32
    const int* __restrict__ tags,              // [B, T] int32
    const int* __restrict__ mask)              // [B, T] int32
{
    __shared__ float pbuf[WPB][2][CRF_K];      // per-warp double-buffered p

    const int warp = threadIdx.x >> 5;
    const int lane = threadIdx.x & 31;
    const int b = blockIdx.x * WPB + warp;
    const unsigned FULL = 0xffffffffu;

    const float* em = emissions + (size_t)b * CRF_T * CRF_K;
    const int* tg = tags + (size_t)b * CRF_T;
    const int* mk = mask + (size_t)b * CRF_T;

    // ---------------- numerator (gold-path score) ----------------
    float part = 0.f;
    int cnt = 0;
    for (int t = lane; t < CRF_T; t += 32) {
        int m = (mk[t] != 0) ? 1 : 0;
        cnt += m;
        if (t > 0 && m) {
            int tag  = tg[t];
            int ptag = tg[t - 1];
            part += em[t * CRF_K + tag] + transitions[ptag * CRF_K + tag];
        }
    }
    #pragma unroll
    for (int off = 16; off; off >>= 1) {
        part += __shfl_xor_sync(FULL, part, off);
        cnt  += __shfl_xor_sync(FULL, cnt,  off);
    }
    float numer = 0.f;
    if (lane == 0) {
        int tag0 = tg[0];
        numer = part + em[tag0] + start_t[tag0];
        numer += end_t[tg[cnt - 1]];
    }

    // ---------------- E = exp(transitions), 2 columns per thread in registers ----------------
    float E0[CRF_K];
    float E1[CRF_K];
    #pragma unroll
    for (int i = 0; i < CRF_K; i++) {
        E0[i] = __expf(transitions[i * CRF_K + lane]);
        E1[i] = __expf(transitions[i * CRF_K + lane + 32]);
    }

    // ---------------- forward recursion ----------------
    // true alpha_j = C + a_j; per step rescale by lane-0's a0 (ref).
    float a0 = em[lane]      + start_t[lane];
    float a1 = em[lane + 32] + start_t[lane + 32];
    float C = 0.f;

    // distance-2 emission/mask pipeline
    float ec0 = em[CRF_K + lane],       ec1 = em[CRF_K + 32 + lane];        // t = 1
    float en0 = em[2 * CRF_K + lane],   en1 = em[2 * CRF_K + 32 + lane];    // t = 2
    int mc = mk[1];
    int mn = mk[2];

    for (int t = 1; t < CRF_T; ++t) {
        // prefetch t+2
        float ep0 = 0.f, ep1 = 0.f;
        int mp = 0;
        if (t + 2 < CRF_T) {
            ep0 = em[(t + 2) * CRF_K + lane];
            ep1 = em[(t + 2) * CRF_K + 32 + lane];
            mp  = mk[t + 2];
        }

        float ref = __shfl_sync(FULL, a0, 0);
        float p0 = __expf(a0 - ref);
        float p1 = __expf(a1 - ref);

        float* pb = pbuf[warp][t & 1];
        pb[lane]      = p0;
        pb[lane + 32] = p1;
        __syncwarp();

        const float4* pv4 = (const float4*)pb;
        float s0a = 0.f, s0b = 0.f, s1a = 0.f, s1b = 0.f;
        #pragma unroll
        for (int q = 0; q < 16; q++) {
            float4 v = pv4[q];          // broadcast LDS.128, conflict-free
            int i = q * 4;
            s0a = fmaf(v.x, E0[i],     s0a);
            s0b = fmaf(v.y, E0[i + 1], s0b);
            s0a = fmaf(v.z, E0[i + 2], s0a);
            s0b = fmaf(v.w, E0[i + 3], s0b);
            s1a = fmaf(v.x, E1[i],     s1a);
            s1b = fmaf(v.y, E1[i + 1], s1b);
            s1a = fmaf(v.z, E1[i + 2], s1a);
            s1b = fmaf(v.w, E1[i + 3], s1b);
        }

        float na0 = ec0 + __logf(s0a + s0b);
        float na1 = ec1 + __logf(s1a + s1b);

        bool mm = (mc != 0);
        a0 = mm ? na0 : a0;
        a1 = mm ? na1 : a1;
        C  = mm ? C + ref : C;

        ec0 = en0; ec1 = en1; en0 = ep0; en1 = ep1;
        mc = mn; mn = mp;
    }

    // ---------------- final logsumexp with end transitions (exact, once) ----------------
    float f0 = a0 + end_t[lane];
    float f1 = a1 + end_t[lane + 32];
    float m2 = fmaxf(f0, f1);
    #pragma unroll
    for (int off = 16; off; off >>= 1)
        m2 = fmaxf(m2, __shfl_xor_sync(FULL, m2, off));
    float s = __expf(f0 - m2) + __expf(f1 - m2);
    #pragma unroll
    for (int off = 16; off; off >>= 1)
        s += __shfl_xor_sync(FULL, s, off);

    if (lane == 0) {
        float denom = C + m2 + __logf(s);
        g_per_batch[b] = denom - numer;
    }
}

__global__ void crf_reduce_kernel(float* __restrict__ out)
{
    __shared__ float sh[CRF_B];
    int t = threadIdx.x;
    sh[t] = g_per_batch[t];
    __syncthreads();
    #pragma unroll
    for (int s = CRF_B / 2; s > 0; s >>= 1) {
        if (t < s) sh[t] += sh[t + s];
        __syncthreads();
    }
    if (t == 0) out[0] = sh[0] * (1.0f / (float)CRF_B);
}

extern "C" void kernel_launch(void* const* d_in, const int* in_sizes, int n_in,
                              void* d_out, int out_size)
{
    const float* emissions   = (const float*)d_in[0];
    const float* transitions = (const float*)d_in[1];
    const float* start_t     = (const float*)d_in[2];
    const float* end_t       = (const float*)d_in[3];
    const int* tags          = (const int*)d_in[4];
    const int* mask          = (const int*)d_in[5];

    crf_forward_kernel<<<CRF_B / WPB, 32 * WPB>>>(emissions, transitions, start_t, end_t, tags, mask);
    crf_reduce_kernel<<<1, CRF_B>>>((float*)d_out);
}